// round 5
// baseline (speedup 1.0000x reference)
#include <cuda_runtime.h>
#include <cstddef>

#define NN 3072
#define NE 30720
#define NG 16
#define TW 6      // towers
#define FOUT 50

// ---------------- device scratch (no allocs allowed) ----------------
__device__ int   d_deg[NN];
__device__ int   d_cur[NN];
__device__ int   d_off[NN + 1];
__device__ int   d_csr[NE];
__device__ float d_avglog;
__device__ float d_degc[NN], d_amp[NN], d_att[NN];

__device__ float d_AB[(size_t)NN * 3600];     // [N, 2*TF] (A | B), max TF=1800
__device__ float d_WAB[300 * 3600];           // packed [F, 2*TF]
__device__ float d_bAB[3600];
__device__ float d_Cw[2 * 1800];
__device__ float d_cb[1800];
__device__ float d_Wp[TW * 1200 * 150];       // packed post weights (agg blocks)
__device__ float d_agg[(size_t)NN * 7200];    // [N, T, 4F]
__device__ float d_Yh[(size_t)NN * 300];
__device__ float d_Ya[(size_t)NN * 900];      // [N, T, 150]
__device__ float d_o[(size_t)NN * 300];
__device__ float d_h[(size_t)NN * 300];
__device__ float d_g[NG * 300];
__device__ float d_g1[NG * 600];
__device__ float d_g2[NG * 300];

// ---------------- precompute kernels ----------------
__global__ void k_init() {
    int n = blockIdx.x * blockDim.x + threadIdx.x;
    if (n < NN) { d_deg[n] = 0; d_cur[n] = 0; }
}

__global__ void k_count(const int* __restrict__ dst) {
    int e = blockIdx.x * blockDim.x + threadIdx.x;
    if (e < NE) atomicAdd(&d_deg[dst[e]], 1);
}

__global__ void k_avglog(const float* __restrict__ hist) {
    __shared__ float sA[64], sH[64];
    int t = threadIdx.x;
    float h = hist[t];
    sA[t] = logf((float)t + 1.0f) * h;
    sH[t] = h;
    __syncthreads();
    for (int o = 32; o > 0; o >>= 1) {
        if (t < o) { sA[t] += sA[t + o]; sH[t] += sH[t + o]; }
        __syncthreads();
    }
    if (t == 0) d_avglog = sA[0] / sH[0];
}

__global__ void k_scan() {   // 1024 threads, 3 nodes each
    __shared__ int sh[1024];
    int tid = threadIdx.x;
    int b = tid * 3;
    int s0 = d_deg[b], s1 = d_deg[b + 1], s2 = d_deg[b + 2];
    int local = s0 + s1 + s2;
    sh[tid] = local;
    __syncthreads();
    for (int o = 1; o < 1024; o <<= 1) {
        int v = (tid >= o) ? sh[tid - o] : 0;
        __syncthreads();
        sh[tid] += v;
        __syncthreads();
    }
    int excl = sh[tid] - local;
    d_off[b]     = excl;
    d_off[b + 1] = excl + s0;
    d_off[b + 2] = excl + s0 + s1;
    if (tid == 1023) d_off[NN] = sh[1023];
}

__global__ void k_scalars() {
    int n = blockIdx.x * blockDim.x + threadIdx.x;
    if (n >= NN) return;
    float dc = (float)max(d_deg[n], 1);
    d_degc[n] = dc;
    float la = logf(dc + 1.0f);
    d_amp[n] = la / d_avglog;
    d_att[n] = d_avglog / la;
}

__global__ void k_scatter(const int* __restrict__ dst) {
    int e = blockIdx.x * blockDim.x + threadIdx.x;
    if (e >= NE) return;
    int d = dst[e];
    int pos = d_off[d] + atomicAdd(&d_cur[d], 1);
    d_csr[pos] = e;
}

__global__ void k_sortseg() {   // deterministic edge order per node
    int n = blockIdx.x * blockDim.x + threadIdx.x;
    if (n >= NN) return;
    int s = d_off[n], e = d_off[n + 1];
    for (int i = s + 1; i < e; i++) {
        int key = d_csr[i];
        int j = i - 1;
        while (j >= s && d_csr[j] > key) { d_csr[j + 1] = d_csr[j]; j--; }
        d_csr[j + 1] = key;
    }
}

// ---------------- per-layer packing ----------------
// WAB[j, c] packed [F, 2*TF]: c<TF -> prew[t, j, f];  c>=TF -> prew[t, F+j, f]
__global__ void k_pack_wab(const float* __restrict__ prew, int F) {
    int TF = TW * F;
    int tot = F * 2 * TF;
    int idx = blockIdx.x * blockDim.x + threadIdx.x;
    if (idx >= tot) return;
    int j = idx / (2 * TF);
    int c = idx - j * (2 * TF);
    int cc = (c < TF) ? c : c - TF;
    int t = cc / F, f = cc - t * F;
    int r = (c < TF) ? j : (F + j);
    d_WAB[idx] = prew[((size_t)(t * 3 * F + r)) * F + f];
}

__global__ void k_pack_bab(const float* __restrict__ preb, int F) {
    int TF = TW * F;
    int c = blockIdx.x * blockDim.x + threadIdx.x;
    if (c >= 2 * TF) return;
    d_bAB[c] = (c < TF) ? preb[c] : 0.0f;
}

// compose edge path:  Cw[k][c] = sum_j ew[k,j]*prew[t,2F+j,f] ; cb = eb-part
__global__ void k_pack_cw(const float* __restrict__ ew, const float* __restrict__ eb,
                          const float* __restrict__ prew, int F) {
    int TF = TW * F;
    int c = blockIdx.x * blockDim.x + threadIdx.x;
    if (c >= TF) return;
    int t = c / F, f = c - t * F;
    const float* pr = prew + ((size_t)(t * 3 * F + 2 * F)) * F + f;
    float a0 = 0.f, a1 = 0.f, ab = 0.f;
    for (int j = 0; j < F; j++) {
        float w = pr[(size_t)j * F];
        a0 += ew[j] * w;
        a1 += ew[F + j] * w;
        ab += eb[j] * w;
    }
    d_Cw[c] = a0; d_Cw[TF + c] = a1; d_cb[c] = ab;
}

// Wp[t][r][k*50+o] = postw[t, F + k*4F + r, o]   (plain / amp / att blocks)
__global__ void k_pack_wp(const float* __restrict__ postw, int F) {
    int F4 = 4 * F;
    int tot = TW * F4 * 150;
    int idx = blockIdx.x * blockDim.x + threadIdx.x;
    if (idx >= tot) return;
    int t = idx / (F4 * 150);
    int rem = idx - t * (F4 * 150);
    int r = rem / 150;
    int q = rem - r * 150;
    int k = q / 50, o = q - k * 50;
    d_Wp[idx] = postw[((size_t)(t * 13 * F + F + k * F4 + r)) * 50 + o];
}

// ---------------- aggregation (mean / min / max / std) ----------------
__global__ void k_agg(const int* __restrict__ src, const float* __restrict__ eattr, int F) {
    int TF = TW * F, ABW = 2 * TF;
    int n = blockIdx.y;
    int c = blockIdx.x * blockDim.x + threadIdx.x;
    if (c >= TF) return;
    float a  = d_AB[(size_t)n * ABW + c];
    float w0 = d_Cw[c], w1 = d_Cw[TF + c], wb = d_cb[c];
    int s = d_off[n], e = d_off[n + 1];
    float sum = 0.f, ss = 0.f, mn = 3.402823466e38f, mx = -3.402823466e38f;
    for (int p = s; p < e; p++) {
        int eid = d_csr[p];
        int sj = src[eid];
        float v = a + d_AB[(size_t)sj * ABW + TF + c]
                + eattr[2 * eid] * w0 + eattr[2 * eid + 1] * w1 + wb;
        sum += v; ss += v * v;
        mn = fminf(mn, v); mx = fmaxf(mx, v);
    }
    if (e == s) { mn = 0.f; mx = 0.f; }
    float dc = d_degc[n];
    float mean = sum / dc;
    float var = fmaxf(ss / dc - mean * mean, 0.f);
    int t = c / F, f = c - t * F;
    float* o = d_agg + (size_t)n * (4 * TF) + (size_t)t * 4 * F;
    o[f]         = mean;
    o[F + f]     = mn;
    o[2 * F + f] = mx;
    o[3 * F + f] = sqrtf(var + 1e-5f);
}

// out[n, t*50+o] = Yh + Ya_plain + amp*Ya_amp + att*Ya_att
__global__ void k_combine() {
    int idx = blockIdx.x * blockDim.x + threadIdx.x;
    if (idx >= NN * 300) return;
    int n = idx / 300, c = idx - n * 300;
    int t = c / 50, o = c - t * 50;
    const float* ya = d_Ya + (size_t)n * 900 + t * 150;
    d_o[idx] = d_Yh[idx] + ya[o] + d_amp[n] * ya[50 + o] + d_att[n] * ya[100 + o];
}

// ---------------- generic batched fp32 GEMM: C = A@B (+bias)(+relu) ----------------
__global__ void k_gemm(int M, int Nd, int K,
                       const float* __restrict__ A, int lda, long long sA,
                       const float* __restrict__ B, int ldb, long long sB,
                       float* __restrict__ C, int ldc, long long sC,
                       const float* __restrict__ bias, long long sBias, int relu) {
    A += (size_t)blockIdx.z * sA;
    B += (size_t)blockIdx.z * sB;
    C += (size_t)blockIdx.z * sC;
    if (bias) bias += (size_t)blockIdx.z * sBias;
    __shared__ float As[16][64];
    __shared__ float Bs[16][64];
    int tid = threadIdx.x;
    int tx = tid & 15, ty = tid >> 4;
    int row0 = blockIdx.y * 64, col0 = blockIdx.x * 64;
    float acc[4][4] = {};
    int la_r = tid >> 2;           // 0..63
    int la_k = (tid & 3) * 4;      // 0,4,8,12
    int lb_k = tid >> 4;           // 0..15
    int lb_n = (tid & 15) * 4;     // 0..60

    for (int k0 = 0; k0 < K; k0 += 16) {
        int ar = row0 + la_r, ak = k0 + la_k;
        float4 av = make_float4(0.f, 0.f, 0.f, 0.f);
        if (ar < M) {
            const float* ap = A + (size_t)ar * lda + ak;
            if (ak + 3 < K) { av.x = ap[0]; av.y = ap[1]; av.z = ap[2]; av.w = ap[3]; }
            else {
                if (ak     < K) av.x = ap[0];
                if (ak + 1 < K) av.y = ap[1];
                if (ak + 2 < K) av.z = ap[2];
                if (ak + 3 < K) av.w = ap[3];
            }
        }
        As[la_k + 0][la_r] = av.x;
        As[la_k + 1][la_r] = av.y;
        As[la_k + 2][la_r] = av.z;
        As[la_k + 3][la_r] = av.w;

        int bk = k0 + lb_k, bn = col0 + lb_n;
        float4 bv = make_float4(0.f, 0.f, 0.f, 0.f);
        if (bk < K) {
            const float* bp = B + (size_t)bk * ldb + bn;
            if (bn + 3 < Nd) { bv.x = bp[0]; bv.y = bp[1]; bv.z = bp[2]; bv.w = bp[3]; }
            else {
                if (bn     < Nd) bv.x = bp[0];
                if (bn + 1 < Nd) bv.y = bp[1];
                if (bn + 2 < Nd) bv.z = bp[2];
                if (bn + 3 < Nd) bv.w = bp[3];
            }
        }
        *(float4*)&Bs[lb_k][lb_n] = bv;
        __syncthreads();

        #pragma unroll
        for (int kk = 0; kk < 16; kk++) {
            float4 a4 = *(const float4*)&As[kk][ty * 4];
            float4 b4 = *(const float4*)&Bs[kk][tx * 4];
            float a[4] = {a4.x, a4.y, a4.z, a4.w};
            float b[4] = {b4.x, b4.y, b4.z, b4.w};
            #pragma unroll
            for (int i = 0; i < 4; i++)
                #pragma unroll
                for (int j = 0; j < 4; j++)
                    acc[i][j] += a[i] * b[j];
        }
        __syncthreads();
    }
    #pragma unroll
    for (int i = 0; i < 4; i++) {
        int r = row0 + ty * 4 + i;
        if (r >= M) continue;
        #pragma unroll
        for (int j = 0; j < 4; j++) {
            int cN = col0 + tx * 4 + j;
            if (cN >= Nd) continue;
            float v = acc[i][j];
            if (bias) v += bias[cN];
            if (relu) v = fmaxf(v, 0.f);
            C[(size_t)r * ldc + cN] = v;
        }
    }
}

// ---------------- pooling ----------------
__global__ void k_pool(const int* __restrict__ batch) {
    int g = blockIdx.x;      // 16
    int c = threadIdx.x;     // 300
    float acc = 0.f;
    for (int n = 0; n < NN; n++)
        if (batch[n] == g) acc += d_h[(size_t)n * 300 + c];
    d_g[g * 300 + c] = acc;
}

// ---------------- host ----------------
extern "C" void kernel_launch(void* const* d_in, const int* in_sizes, int n_in,
                              void* d_out, int out_size) {
    const float* x      = (const float*)d_in[0];
    const float* eattr  = (const float*)d_in[1];
    const int*   eidx   = (const int*)  d_in[2];
    const int*   batch  = (const int*)  d_in[3];
    const float* dhist  = (const float*)d_in[4];
    const float* ew0    = (const float*)d_in[5];
    const float* eb0    = (const float*)d_in[6];
    const float* prew0  = (const float*)d_in[7];
    const float* preb0  = (const float*)d_in[8];
    const float* postw0 = (const float*)d_in[9];
    const float* postb0 = (const float*)d_in[10];
    const float* linw0  = (const float*)d_in[11];
    const float* linb0  = (const float*)d_in[12];
    const float* ew     = (const float*)d_in[13];
    const float* eb     = (const float*)d_in[14];
    const float* prew   = (const float*)d_in[15];
    const float* preb   = (const float*)d_in[16];
    const float* postw  = (const float*)d_in[17];
    const float* postb  = (const float*)d_in[18];
    const float* linw   = (const float*)d_in[19];
    const float* linb   = (const float*)d_in[20];
    const float* hw1    = (const float*)d_in[21];
    const float* hb1    = (const float*)d_in[22];
    const float* hw2    = (const float*)d_in[23];
    const float* hb2    = (const float*)d_in[24];
    const float* hw3    = (const float*)d_in[25];
    const float* hb3    = (const float*)d_in[26];

    const int* srcA = eidx;
    const int* dstA = eidx + NE;

    float *pAB, *pWAB, *pbAB, *pWp, *pAgg, *pYh, *pYa, *pO, *pH, *pG, *pG1, *pG2;
    cudaGetSymbolAddress((void**)&pAB,  d_AB);
    cudaGetSymbolAddress((void**)&pWAB, d_WAB);
    cudaGetSymbolAddress((void**)&pbAB, d_bAB);
    cudaGetSymbolAddress((void**)&pWp,  d_Wp);
    cudaGetSymbolAddress((void**)&pAgg, d_agg);
    cudaGetSymbolAddress((void**)&pYh,  d_Yh);
    cudaGetSymbolAddress((void**)&pYa,  d_Ya);
    cudaGetSymbolAddress((void**)&pO,   d_o);
    cudaGetSymbolAddress((void**)&pH,   d_h);
    cudaGetSymbolAddress((void**)&pG,   d_g);
    cudaGetSymbolAddress((void**)&pG1,  d_g1);
    cudaGetSymbolAddress((void**)&pG2,  d_g2);

    // ---- graph preprocessing (deterministic CSR) ----
    k_init<<<(NN + 255) / 256, 256>>>();
    k_count<<<(NE + 255) / 256, 256>>>(dstA);
    k_avglog<<<1, 64>>>(dhist);
    k_scan<<<1, 1024>>>();
    k_scalars<<<(NN + 255) / 256, 256>>>();
    k_scatter<<<(NE + 255) / 256, 256>>>(dstA);
    k_sortseg<<<(NN + 255) / 256, 256>>>();

    auto layer = [&](int F, const float* hin,
                     const float* ewL, const float* ebL,
                     const float* prewL, const float* prebL,
                     const float* postwL, const float* postbL,
                     const float* linwL, const float* linbL, int relu) {
        int TF = TW * F;
        k_pack_wab<<<(F * 2 * TF + 255) / 256, 256>>>(prewL, F);
        k_pack_bab<<<(2 * TF + 255) / 256, 256>>>(prebL, F);
        k_pack_cw<<<(TF + 255) / 256, 256>>>(ewL, ebL, prewL, F);
        k_pack_wp<<<(TW * 4 * F * 150 + 255) / 256, 256>>>(postwL, F);

        // AB = h @ WAB + biasAB      [N, 2TF]
        {
            dim3 g((2 * TF + 63) / 64, (NN + 63) / 64, 1);
            k_gemm<<<g, 256>>>(NN, 2 * TF, F, hin, F, 0, pWAB, 2 * TF, 0,
                               pAB, 2 * TF, 0, pbAB, 0, 0);
        }
        // aggregation -> agg [N, T, 4F]
        {
            dim3 g((TF + 255) / 256, NN, 1);
            k_agg<<<g, 256>>>(srcA, eattr, F);
        }
        // Ya[n,t,150] = agg_t @ Wp_t   (batched over towers)
        {
            dim3 g((150 + 63) / 64, (NN + 63) / 64, TW);
            k_gemm<<<g, 256>>>(NN, 150, 4 * F, pAgg, 4 * TF, 4 * F,
                               pWp, 150, (long long)4 * F * 150,
                               pYa, 900, 150, nullptr, 0, 0);
        }
        // Yh[n,t,50] = h @ postw[t, 0:F, :] + postb[t]
        {
            dim3 g((50 + 63) / 64, (NN + 63) / 64, TW);
            k_gemm<<<g, 256>>>(NN, 50, F, hin, F, 0,
                               postwL, 50, (long long)13 * F * 50,
                               pYh, 300, 50, postbL, 50, 0);
        }
        k_combine<<<(NN * 300 + 255) / 256, 256>>>();
        // h_next = (out @ linw + linb)  [+relu]
        {
            dim3 g((300 + 63) / 64, (NN + 63) / 64, 1);
            k_gemm<<<g, 256>>>(NN, 300, 300, pO, 300, 0, linwL, 300, 0,
                               pH, 300, 0, linbL, 0, relu);
        }
    };

    // layer 0 (F=32), relu
    layer(32, x, ew0, eb0, prew0, preb0, postw0, postb0, linw0, linb0, 1);
    // layers 1..4 (F=300), relu on all but last
    for (int l = 0; l < 4; l++) {
        layer(300, pH,
              ew + (size_t)l * 600, eb + (size_t)l * 300,
              prew + (size_t)l * 1620000, preb + (size_t)l * 1800,
              postw + (size_t)l * 1170000, postb + (size_t)l * 300,
              linw + (size_t)l * 90000, linb + (size_t)l * 300,
              (l < 3) ? 1 : 0);
    }

    // global_add_pool + head MLP
    k_pool<<<NG, 300>>>(batch);
    {
        dim3 g((600 + 63) / 64, 1, 1);
        k_gemm<<<g, 256>>>(NG, 600, 300, pG, 300, 0, hw1, 600, 0, pG1, 600, 0, hb1, 0, 1);
    }
    {
        dim3 g((300 + 63) / 64, 1, 1);
        k_gemm<<<g, 256>>>(NG, 300, 600, pG1, 600, 0, hw2, 300, 0, pG2, 300, 0, hb2, 0, 1);
    }
    {
        dim3 g(1, 1, 1);
        k_gemm<<<g, 256>>>(NG, 1, 300, pG2, 300, 0, hw3, 1, 0, (float*)d_out, 1, 0, hb3, 0, 1);
    }
}

// round 6
// speedup vs baseline: 1.2439x; 1.2439x over previous
#include <cuda_runtime.h>
#include <cstddef>

#define NN 3072
#define NE 30720
#define NG 16
#define TW 6      // towers
#define FOUT 50

// ---------------- device scratch (no allocs allowed) ----------------
__device__ int   d_deg[NN];
__device__ int   d_cur[NN];
__device__ int   d_off[NN + 1];
__device__ int   d_csr[NE];
__device__ float d_avglog;
__device__ float d_degc[NN], d_amp[NN], d_att[NN];

__device__ float d_AB[(size_t)NN * 3600];       // [N, 2*TF] (A | B), max TF=1800
__device__ float d_WAB[300 * 3712];             // packed [F, pad(2*TF)]
__device__ float d_bAB[3600];
__device__ float d_Cw[2 * 1800];
__device__ float d_cb[1800];
__device__ float d_Wp[(size_t)TW * 1200 * 192]; // packed post weights (agg blocks), padded 150->192
__device__ float d_Wh[(size_t)TW * 300 * 64];   // packed post weights (h block),  padded 50->64
__device__ float d_agg[(size_t)NN * 7200];      // [N, T, 4F]
__device__ float d_Yh[(size_t)NN * 300];
__device__ float d_Ya[(size_t)NN * 900];        // [N, T, 150]
__device__ float d_o[(size_t)NN * 300];
__device__ float d_h[(size_t)NN * 300];
__device__ float d_g[NG * 300];
__device__ float d_g1[NG * 600];
__device__ float d_g2[NG * 300];

// ---------------- f32x2 helpers ----------------
__device__ __forceinline__ unsigned long long pack2(float x, float y) {
    unsigned long long r;
    asm("mov.b64 %0, {%1,%2};" : "=l"(r) : "f"(x), "f"(y));
    return r;
}
__device__ __forceinline__ void fma2(unsigned long long& d, unsigned long long a, unsigned long long b) {
    asm("fma.rn.f32x2 %0, %1, %2, %0;" : "+l"(d) : "l"(a), "l"(b));
}
__device__ __forceinline__ float2 unpack2(unsigned long long v) {
    float2 f;
    asm("mov.b64 {%0,%1}, %2;" : "=f"(f.x), "=f"(f.y) : "l"(v));
    return f;
}

// ---------------- precompute kernels ----------------
__global__ void k_init() {
    int n = blockIdx.x * blockDim.x + threadIdx.x;
    if (n < NN) { d_deg[n] = 0; d_cur[n] = 0; }
}

__global__ void k_count(const int* __restrict__ dst) {
    int e = blockIdx.x * blockDim.x + threadIdx.x;
    if (e < NE) atomicAdd(&d_deg[dst[e]], 1);
}

__global__ void k_avglog(const float* __restrict__ hist) {
    __shared__ float sA[64], sH[64];
    int t = threadIdx.x;
    float h = hist[t];
    sA[t] = logf((float)t + 1.0f) * h;
    sH[t] = h;
    __syncthreads();
    for (int o = 32; o > 0; o >>= 1) {
        if (t < o) { sA[t] += sA[t + o]; sH[t] += sH[t + o]; }
        __syncthreads();
    }
    if (t == 0) d_avglog = sA[0] / sH[0];
}

__global__ void k_scan() {   // 1024 threads, 3 nodes each
    __shared__ int sh[1024];
    int tid = threadIdx.x;
    int b = tid * 3;
    int s0 = d_deg[b], s1 = d_deg[b + 1], s2 = d_deg[b + 2];
    int local = s0 + s1 + s2;
    sh[tid] = local;
    __syncthreads();
    for (int o = 1; o < 1024; o <<= 1) {
        int v = (tid >= o) ? sh[tid - o] : 0;
        __syncthreads();
        sh[tid] += v;
        __syncthreads();
    }
    int excl = sh[tid] - local;
    d_off[b]     = excl;
    d_off[b + 1] = excl + s0;
    d_off[b + 2] = excl + s0 + s1;
    if (tid == 1023) d_off[NN] = sh[1023];
}

__global__ void k_scalars() {
    int n = blockIdx.x * blockDim.x + threadIdx.x;
    if (n >= NN) return;
    float dc = (float)max(d_deg[n], 1);
    d_degc[n] = dc;
    float la = logf(dc + 1.0f);
    d_amp[n] = la / d_avglog;
    d_att[n] = d_avglog / la;
}

__global__ void k_scatter(const int* __restrict__ dst) {
    int e = blockIdx.x * blockDim.x + threadIdx.x;
    if (e >= NE) return;
    int d = dst[e];
    int pos = d_off[d] + atomicAdd(&d_cur[d], 1);
    d_csr[pos] = e;
}

__global__ void k_sortseg() {   // deterministic edge order per node
    int n = blockIdx.x * blockDim.x + threadIdx.x;
    if (n >= NN) return;
    int s = d_off[n], e = d_off[n + 1];
    for (int i = s + 1; i < e; i++) {
        int key = d_csr[i];
        int j = i - 1;
        while (j >= s && d_csr[j] > key) { d_csr[j + 1] = d_csr[j]; j--; }
        d_csr[j + 1] = key;
    }
}

// ---------------- per-layer packing ----------------
// WAB[j, c] packed [F, P]: c<TF -> prew[t, j, f];  TF<=c<2TF -> prew[t, F+j, f]; else 0
__global__ void k_pack_wab(const float* __restrict__ prew, int F, int P) {
    int TF = TW * F;
    int tot = F * P;
    int idx = blockIdx.x * blockDim.x + threadIdx.x;
    if (idx >= tot) return;
    int j = idx / P;
    int c = idx - j * P;
    float v = 0.0f;
    if (c < 2 * TF) {
        int cc = (c < TF) ? c : c - TF;
        int t = cc / F, f = cc - t * F;
        int r = (c < TF) ? j : (F + j);
        v = prew[((size_t)(t * 3 * F + r)) * F + f];
    }
    d_WAB[idx] = v;
}

__global__ void k_pack_bab(const float* __restrict__ preb, int F) {
    int TF = TW * F;
    int c = blockIdx.x * blockDim.x + threadIdx.x;
    if (c >= 2 * TF) return;
    d_bAB[c] = (c < TF) ? preb[c] : 0.0f;
}

// compose edge path:  Cw[k][c] = sum_j ew[k,j]*prew[t,2F+j,f] ; cb = eb-part
__global__ void k_pack_cw(const float* __restrict__ ew, const float* __restrict__ eb,
                          const float* __restrict__ prew, int F) {
    int TF = TW * F;
    int c = blockIdx.x * blockDim.x + threadIdx.x;
    if (c >= TF) return;
    int t = c / F, f = c - t * F;
    const float* pr = prew + ((size_t)(t * 3 * F + 2 * F)) * F + f;
    float a0 = 0.f, a1 = 0.f, ab = 0.f;
    for (int j = 0; j < F; j++) {
        float w = pr[(size_t)j * F];
        a0 += ew[j] * w;
        a1 += ew[F + j] * w;
        ab += eb[j] * w;
    }
    d_Cw[c] = a0; d_Cw[TF + c] = a1; d_cb[c] = ab;
}

// Wp[t][r][q] (q<150): postw[t, F + (q/50)*4F + r, q%50]; q in [150,192): 0
__global__ void k_pack_wp(const float* __restrict__ postw, int F) {
    int F4 = 4 * F;
    int tot = TW * F4 * 192;
    int idx = blockIdx.x * blockDim.x + threadIdx.x;
    if (idx >= tot) return;
    int t = idx / (F4 * 192);
    int rem = idx - t * (F4 * 192);
    int r = rem / 192;
    int q = rem - r * 192;
    float v = 0.0f;
    if (q < 150) {
        int k = q / 50, o = q - k * 50;
        v = postw[((size_t)(t * 13 * F + F + k * F4 + r)) * 50 + o];
    }
    d_Wp[idx] = v;
}

// Wh[t][r][o] (o<50): postw[t, r, o]; o in [50,64): 0
__global__ void k_pack_wh(const float* __restrict__ postw, int F) {
    int tot = TW * F * 64;
    int idx = blockIdx.x * blockDim.x + threadIdx.x;
    if (idx >= tot) return;
    int t = idx / (F * 64);
    int rem = idx - t * (F * 64);
    int r = rem / 64;
    int o = rem - r * 64;
    d_Wh[idx] = (o < 50) ? postw[((size_t)(t * 13 * F + r)) * 50 + o] : 0.0f;
}

// ---------------- aggregation (mean / min / max / std) ----------------
__global__ void k_agg(const int* __restrict__ src, const float* __restrict__ eattr, int F) {
    int TF = TW * F, ABW = 2 * TF;
    int n = blockIdx.y;
    int c = blockIdx.x * blockDim.x + threadIdx.x;
    if (c >= TF) return;
    float a  = d_AB[(size_t)n * ABW + c];
    float w0 = d_Cw[c], w1 = d_Cw[TF + c], wb = d_cb[c];
    int s = d_off[n], e = d_off[n + 1];
    float sum = 0.f, ss = 0.f, mn = 3.402823466e38f, mx = -3.402823466e38f;
    for (int p = s; p < e; p++) {
        int eid = d_csr[p];
        int sj = src[eid];
        float v = a + d_AB[(size_t)sj * ABW + TF + c]
                + eattr[2 * eid] * w0 + eattr[2 * eid + 1] * w1 + wb;
        sum += v; ss += v * v;
        mn = fminf(mn, v); mx = fmaxf(mx, v);
    }
    if (e == s) { mn = 0.f; mx = 0.f; }
    float dc = d_degc[n];
    float mean = sum / dc;
    float var = fmaxf(ss / dc - mean * mean, 0.f);
    int t = c / F, f = c - t * F;
    float* o = d_agg + (size_t)n * (4 * TF) + (size_t)t * 4 * F;
    o[f]         = mean;
    o[F + f]     = mn;
    o[2 * F + f] = mx;
    o[3 * F + f] = sqrtf(var + 1e-5f);
}

// out[n, t*50+o] = Yh + Ya_plain + amp*Ya_amp + att*Ya_att
__global__ void k_combine() {
    int idx = blockIdx.x * blockDim.x + threadIdx.x;
    if (idx >= NN * 300) return;
    int n = idx / 300, c = idx - n * 300;
    int t = c / 50, o = c - t * 50;
    const float* ya = d_Ya + (size_t)n * 900 + t * 150;
    d_o[idx] = d_Yh[idx] + ya[o] + d_amp[n] * ya[50 + o] + d_att[n] * ya[100 + o];
}

// ---------------- f32x2 double-buffered GEMM: C = A@B (+bias)(+relu) ----------------
// BM x BN tile, BK=8, 256 threads, TM x TN microtile. Requires ldb%4==0,
// K%4==0, 16B-aligned A/B base+lda. Ndb = physically safe B width, Nd = logical.
template<int BM, int BN, int TM, int TN>
__global__ void __launch_bounds__(256, 2)
k_gemm2(int M, int Nd, int Ndb, int K,
        const float* __restrict__ A, int lda, long long sA,
        const float* __restrict__ B, int ldb, long long sB,
        float* __restrict__ C, int ldc, long long sC,
        const float* __restrict__ bias, long long sBias, int relu) {
    constexpr int BK  = 8;
    constexpr int TN2 = TN / 2;
    A += (size_t)blockIdx.z * sA;
    B += (size_t)blockIdx.z * sB;
    C += (size_t)blockIdx.z * sC;
    if (bias) bias += (size_t)blockIdx.z * sBias;

    __shared__ float As[2][BK][BM + 4];
    __shared__ float Bs[2][BK][BN];

    const int tid = threadIdx.x;
    const int tx = tid & 15, ty = tid >> 4;
    const int row0 = blockIdx.y * BM, col0 = blockIdx.x * BN;

    // A G2S: BK*BM floats, 2 threads per row (float4 along K)
    const int arow = tid >> 1;
    const int akid = (tid & 1) * 4;
    // B G2S: BK*BN floats
    constexpr int THR_B = BK * BN / 4;
    const int brow = tid / (BN / 4);
    const int bcol = (tid % (BN / 4)) * 4;

    unsigned long long acc[TM][TN2];
#pragma unroll
    for (int i = 0; i < TM; i++)
#pragma unroll
        for (int j = 0; j < TN2; j++) acc[i][j] = 0ULL;

    const int S = (K + BK - 1) / BK;

    auto loadA = [&](int k0) -> float4 {
        float4 v = make_float4(0.f, 0.f, 0.f, 0.f);
        int r = row0 + arow, k = k0 + akid;
        if (r < M && k < K) v = *(const float4*)(A + (size_t)r * lda + k);
        return v;
    };
    auto loadB = [&](int k0) -> float4 {
        float4 v = make_float4(0.f, 0.f, 0.f, 0.f);
        if (tid < THR_B) {
            int k = k0 + brow, c = col0 + bcol;
            if (k < K) {
                const float* bp = B + (size_t)k * ldb + c;
                if (c + 3 < Ndb) v = *(const float4*)bp;
                else {
                    if (c     < Ndb) v.x = bp[0];
                    if (c + 1 < Ndb) v.y = bp[1];
                    if (c + 2 < Ndb) v.z = bp[2];
                    if (c + 3 < Ndb) v.w = bp[3];
                }
            }
        }
        return v;
    };

    float4 av = loadA(0), bv = loadB(0);
    // store buf 0
    As[0][akid + 0][arow] = av.x;
    As[0][akid + 1][arow] = av.y;
    As[0][akid + 2][arow] = av.z;
    As[0][akid + 3][arow] = av.w;
    if (tid < THR_B) *(float4*)&Bs[0][brow][bcol] = bv;
    __syncthreads();

    for (int s = 0; s < S; s++) {
        int cur = s & 1;
        if (s + 1 < S) { av = loadA((s + 1) * BK); bv = loadB((s + 1) * BK); }
#pragma unroll
        for (int kk = 0; kk < BK; kk++) {
            float a[TM];
#pragma unroll
            for (int i = 0; i < TM; i += 4)
                *(float4*)&a[i] = *(const float4*)&As[cur][kk][ty * TM + i];
            unsigned long long bb[TN2];
#pragma unroll
            for (int j = 0; j < TN2; j += 2) {
                ulonglong2 t2 = *(const ulonglong2*)&Bs[cur][kk][tx * TN + 2 * j];
                bb[j] = t2.x; bb[j + 1] = t2.y;
            }
#pragma unroll
            for (int i = 0; i < TM; i++) {
                unsigned long long aa = pack2(a[i], a[i]);
#pragma unroll
                for (int j = 0; j < TN2; j++)
                    fma2(acc[i][j], aa, bb[j]);
            }
        }
        if (s + 1 < S) {
            int nxt = 1 - cur;
            As[nxt][akid + 0][arow] = av.x;
            As[nxt][akid + 1][arow] = av.y;
            As[nxt][akid + 2][arow] = av.z;
            As[nxt][akid + 3][arow] = av.w;
            if (tid < THR_B) *(float4*)&Bs[nxt][brow][bcol] = bv;
        }
        __syncthreads();
    }

#pragma unroll
    for (int i = 0; i < TM; i++) {
        int r = row0 + ty * TM + i;
        if (r >= M) continue;
#pragma unroll
        for (int j = 0; j < TN2; j++) {
            float2 v = unpack2(acc[i][j]);
            int c0 = col0 + tx * TN + 2 * j;
            float vx = v.x, vy = v.y;
            if (bias) {
                if (c0     < Nd) vx += bias[c0];
                if (c0 + 1 < Nd) vy += bias[c0 + 1];
            }
            if (relu) { vx = fmaxf(vx, 0.f); vy = fmaxf(vy, 0.f); }
            if (c0     < Nd) C[(size_t)r * ldc + c0]     = vx;
            if (c0 + 1 < Nd) C[(size_t)r * ldc + c0 + 1] = vy;
        }
    }
}

// ---------------- pooling + final head ----------------
__global__ void k_pool(const int* __restrict__ batch) {
    int g = blockIdx.x;      // 16
    int c = threadIdx.x;     // 300
    float acc = 0.f;
    for (int n = 0; n < NN; n++)
        if (batch[n] == g) acc += d_h[(size_t)n * 300 + c];
    d_g[g * 300 + c] = acc;
}

__global__ void k_head3(const float* __restrict__ hw3, const float* __restrict__ hb3,
                        float* __restrict__ out) {
    int g = threadIdx.x >> 5;   // 16 warps
    int l = threadIdx.x & 31;
    float s = 0.f;
    for (int c = l; c < 300; c += 32) s += d_g2[g * 300 + c] * hw3[c];
#pragma unroll
    for (int o = 16; o > 0; o >>= 1) s += __shfl_xor_sync(0xffffffffu, s, o);
    if (l == 0) out[g] = fmaxf(s + hb3[0], 0.f);
}

// ---------------- host ----------------
extern "C" void kernel_launch(void* const* d_in, const int* in_sizes, int n_in,
                              void* d_out, int out_size) {
    const float* x      = (const float*)d_in[0];
    const float* eattr  = (const float*)d_in[1];
    const int*   eidx   = (const int*)  d_in[2];
    const int*   batch  = (const int*)  d_in[3];
    const float* dhist  = (const float*)d_in[4];
    const float* ew0    = (const float*)d_in[5];
    const float* eb0    = (const float*)d_in[6];
    const float* prew0  = (const float*)d_in[7];
    const float* preb0  = (const float*)d_in[8];
    const float* postw0 = (const float*)d_in[9];
    const float* postb0 = (const float*)d_in[10];
    const float* linw0  = (const float*)d_in[11];
    const float* linb0  = (const float*)d_in[12];
    const float* ew     = (const float*)d_in[13];
    const float* eb     = (const float*)d_in[14];
    const float* prew   = (const float*)d_in[15];
    const float* preb   = (const float*)d_in[16];
    const float* postw  = (const float*)d_in[17];
    const float* postb  = (const float*)d_in[18];
    const float* linw   = (const float*)d_in[19];
    const float* linb   = (const float*)d_in[20];
    const float* hw1    = (const float*)d_in[21];
    const float* hb1    = (const float*)d_in[22];
    const float* hw2    = (const float*)d_in[23];
    const float* hb2    = (const float*)d_in[24];
    const float* hw3    = (const float*)d_in[25];
    const float* hb3    = (const float*)d_in[26];

    const int* srcA = eidx;
    const int* dstA = eidx + NE;

    float *pAB, *pWAB, *pbAB, *pWp, *pWh, *pAgg, *pYh, *pYa, *pO, *pH, *pG, *pG1, *pG2;
    cudaGetSymbolAddress((void**)&pAB,  d_AB);
    cudaGetSymbolAddress((void**)&pWAB, d_WAB);
    cudaGetSymbolAddress((void**)&pbAB, d_bAB);
    cudaGetSymbolAddress((void**)&pWp,  d_Wp);
    cudaGetSymbolAddress((void**)&pWh,  d_Wh);
    cudaGetSymbolAddress((void**)&pAgg, d_agg);
    cudaGetSymbolAddress((void**)&pYh,  d_Yh);
    cudaGetSymbolAddress((void**)&pYa,  d_Ya);
    cudaGetSymbolAddress((void**)&pO,   d_o);
    cudaGetSymbolAddress((void**)&pH,   d_h);
    cudaGetSymbolAddress((void**)&pG,   d_g);
    cudaGetSymbolAddress((void**)&pG1,  d_g1);
    cudaGetSymbolAddress((void**)&pG2,  d_g2);

    // ---- graph preprocessing (deterministic CSR) ----
    k_init<<<(NN + 255) / 256, 256>>>();
    k_count<<<(NE + 255) / 256, 256>>>(dstA);
    k_avglog<<<1, 64>>>(dhist);
    k_scan<<<1, 1024>>>();
    k_scalars<<<(NN + 255) / 256, 256>>>();
    k_scatter<<<(NE + 255) / 256, 256>>>(dstA);
    k_sortseg<<<(NN + 255) / 256, 256>>>();

    auto layer = [&](int F, const float* hin,
                     const float* ewL, const float* ebL,
                     const float* prewL, const float* prebL,
                     const float* postwL, const float* postbL,
                     const float* linwL, const float* linbL, int relu) {
        int TF = TW * F;
        int P  = ((2 * TF + 127) / 128) * 128;    // padded AB width (3712 / 384)
        k_pack_wab<<<(F * P + 255) / 256, 256>>>(prewL, F, P);
        k_pack_bab<<<(2 * TF + 255) / 256, 256>>>(prebL, F);
        k_pack_cw<<<(TF + 255) / 256, 256>>>(ewL, ebL, prewL, F);
        k_pack_wp<<<(TW * 4 * F * 192 + 255) / 256, 256>>>(postwL, F);
        k_pack_wh<<<(TW * F * 64 + 255) / 256, 256>>>(postwL, F);

        // AB = h @ WAB + biasAB      [N, 2TF]
        {
            dim3 g(P / 128, NN / 128, 1);
            k_gemm2<128, 128, 8, 8><<<g, 256>>>(NN, 2 * TF, P, F,
                hin, F, 0, pWAB, P, 0, pAB, 2 * TF, 0, pbAB, 0, 0);
        }
        // aggregation -> agg [N, T, 4F]
        {
            dim3 g((TF + 255) / 256, NN, 1);
            k_agg<<<g, 256>>>(srcA, eattr, F);
        }
        // Ya[n,t,150] = agg_t @ Wp_t   (batched over towers, Wp padded to 192)
        {
            dim3 g(3, NN / 128, TW);
            k_gemm2<128, 64, 8, 4><<<g, 256>>>(NN, 150, 192, 4 * F,
                pAgg, 4 * TF, 4 * F, pWp, 192, (long long)4 * F * 192,
                pYa, 900, 150, nullptr, 0, 0);
        }
        // Yh[n,t,50] = h @ Wh_t + postb[t]   (Wh padded to 64)
        {
            dim3 g(1, NN / 128, TW);
            k_gemm2<128, 64, 8, 4><<<g, 256>>>(NN, 50, 64, F,
                hin, F, 0, pWh, 64, (long long)F * 64,
                pYh, 300, 50, postbL, 50, 0);
        }
        k_combine<<<(NN * 300 + 255) / 256, 256>>>();
        // h_next = (out @ linw + linb)  [+relu]
        {
            dim3 g(5, NN / 128, 1);
            k_gemm2<128, 64, 8, 4><<<g, 256>>>(NN, 300, 300, 300,
                pO, 300, 0, linwL, 300, 0, pH, 300, 0, linbL, 0, relu);
        }
    };

    // layer 0 (F=32), relu
    layer(32, x, ew0, eb0, prew0, preb0, postw0, postb0, linw0, linb0, 1);
    // layers 1..4 (F=300), relu on all but last
    for (int l = 0; l < 4; l++) {
        layer(300, pH,
              ew + (size_t)l * 600, eb + (size_t)l * 300,
              prew + (size_t)l * 1620000, preb + (size_t)l * 1800,
              postw + (size_t)l * 1170000, postb + (size_t)l * 300,
              linw + (size_t)l * 90000, linb + (size_t)l * 300,
              (l < 3) ? 1 : 0);
    }

    // global_add_pool + head MLP
    k_pool<<<NG, 300>>>(batch);
    {
        dim3 g(10, 1, 1);
        k_gemm2<128, 64, 8, 4><<<g, 256>>>(NG, 600, 600, 300,
            pG, 300, 0, hw1, 600, 0, pG1, 600, 0, hb1, 0, 1);
    }
    {
        dim3 g(5, 1, 1);
        k_gemm2<128, 64, 8, 4><<<g, 256>>>(NG, 300, 300, 600,
            pG1, 600, 0, hw2, 300, 0, pG2, 300, 0, hb2, 0, 1);
    }
    k_head3<<<1, 512>>>(hw3, hb3, (float*)d_out);
}

// round 7
// speedup vs baseline: 1.7692x; 1.4223x over previous
#include <cuda_runtime.h>
#include <cstddef>

#define NN 3072
#define NE 30720
#define NG 16
#define TW 6      // towers
#define FOUT 50

// ---------------- device scratch (no allocs allowed) ----------------
__device__ int   d_deg[NN];
__device__ int   d_cur[NN];
__device__ int   d_off[NN + 1];
__device__ int   d_csr[NE];
__device__ float d_avglog;
__device__ float d_degc[NN], d_amp[NN], d_att[NN];

__device__ float d_AB[(size_t)NN * 3600];       // [N, 2*TF] (A | B), max TF=1800
__device__ float d_WAB[300 * 3712];             // packed [F, pad(2*TF)]
__device__ float d_bAB[3600];
__device__ float d_Cw[2 * 1800];
__device__ float d_cb[1800];
__device__ float d_Wp[(size_t)TW * 1200 * 192]; // packed post weights (agg blocks), padded 150->192
__device__ float d_Wh[(size_t)TW * 300 * 64];   // packed post weights (h block),  padded 50->64
__device__ float d_agg[(size_t)NN * 7200];      // [N, T, 4F]
__device__ float d_Yh[(size_t)NN * 300];
__device__ float d_Ya[(size_t)NN * 900];        // [N, T, 150]
__device__ float d_o[(size_t)NN * 300];
__device__ float d_h[(size_t)NN * 300];
__device__ float d_g[NG * 300];
__device__ float d_g1[NG * 600];
__device__ float d_g2[NG * 300];

// ---------------- tf32 helpers ----------------
__device__ __forceinline__ float totf32(float x) {
    float y;
    asm("cvt.rna.tf32.f32 %0, %1;" : "=f"(y) : "f"(x));
    return y;
}
__device__ __forceinline__ void mma_tf32(float* d, const unsigned* a, const unsigned* b) {
    asm volatile("mma.sync.aligned.m16n8k8.row.col.f32.tf32.tf32.f32 "
                 "{%0,%1,%2,%3}, {%4,%5,%6,%7}, {%8,%9}, {%0,%1,%2,%3};"
                 : "+f"(d[0]), "+f"(d[1]), "+f"(d[2]), "+f"(d[3])
                 : "r"(a[0]), "r"(a[1]), "r"(a[2]), "r"(a[3]),
                   "r"(b[0]), "r"(b[1]));
}

// ---------------- precompute kernels ----------------
__global__ void k_init() {
    int n = blockIdx.x * blockDim.x + threadIdx.x;
    if (n < NN) { d_deg[n] = 0; d_cur[n] = 0; }
}

__global__ void k_count(const int* __restrict__ dst) {
    int e = blockIdx.x * blockDim.x + threadIdx.x;
    if (e < NE) atomicAdd(&d_deg[dst[e]], 1);
}

__global__ void k_avglog(const float* __restrict__ hist) {
    __shared__ float sA[64], sH[64];
    int t = threadIdx.x;
    float h = hist[t];
    sA[t] = logf((float)t + 1.0f) * h;
    sH[t] = h;
    __syncthreads();
    for (int o = 32; o > 0; o >>= 1) {
        if (t < o) { sA[t] += sA[t + o]; sH[t] += sH[t + o]; }
        __syncthreads();
    }
    if (t == 0) d_avglog = sA[0] / sH[0];
}

__global__ void k_scan() {   // 1024 threads, 3 nodes each
    __shared__ int sh[1024];
    int tid = threadIdx.x;
    int b = tid * 3;
    int s0 = d_deg[b], s1 = d_deg[b + 1], s2 = d_deg[b + 2];
    int local = s0 + s1 + s2;
    sh[tid] = local;
    __syncthreads();
    for (int o = 1; o < 1024; o <<= 1) {
        int v = (tid >= o) ? sh[tid - o] : 0;
        __syncthreads();
        sh[tid] += v;
        __syncthreads();
    }
    int excl = sh[tid] - local;
    d_off[b]     = excl;
    d_off[b + 1] = excl + s0;
    d_off[b + 2] = excl + s0 + s1;
    if (tid == 1023) d_off[NN] = sh[1023];
}

__global__ void k_scalars() {
    int n = blockIdx.x * blockDim.x + threadIdx.x;
    if (n >= NN) return;
    float dc = (float)max(d_deg[n], 1);
    d_degc[n] = dc;
    float la = logf(dc + 1.0f);
    d_amp[n] = la / d_avglog;
    d_att[n] = d_avglog / la;
}

__global__ void k_scatter(const int* __restrict__ dst) {
    int e = blockIdx.x * blockDim.x + threadIdx.x;
    if (e >= NE) return;
    int d = dst[e];
    int pos = d_off[d] + atomicAdd(&d_cur[d], 1);
    d_csr[pos] = e;
}

__global__ void k_sortseg() {   // deterministic edge order per node
    int n = blockIdx.x * blockDim.x + threadIdx.x;
    if (n >= NN) return;
    int s = d_off[n], e = d_off[n + 1];
    for (int i = s + 1; i < e; i++) {
        int key = d_csr[i];
        int j = i - 1;
        while (j >= s && d_csr[j] > key) { d_csr[j + 1] = d_csr[j]; j--; }
        d_csr[j + 1] = key;
    }
}

// ---------------- per-layer packing ----------------
__global__ void k_pack_wab(const float* __restrict__ prew, int F, int P) {
    int TF = TW * F;
    int tot = F * P;
    int idx = blockIdx.x * blockDim.x + threadIdx.x;
    if (idx >= tot) return;
    int j = idx / P;
    int c = idx - j * P;
    float v = 0.0f;
    if (c < 2 * TF) {
        int cc = (c < TF) ? c : c - TF;
        int t = cc / F, f = cc - t * F;
        int r = (c < TF) ? j : (F + j);
        v = prew[((size_t)(t * 3 * F + r)) * F + f];
    }
    d_WAB[idx] = v;
}

__global__ void k_pack_bab(const float* __restrict__ preb, int F) {
    int TF = TW * F;
    int c = blockIdx.x * blockDim.x + threadIdx.x;
    if (c >= 2 * TF) return;
    d_bAB[c] = (c < TF) ? preb[c] : 0.0f;
}

__global__ void k_pack_cw(const float* __restrict__ ew, const float* __restrict__ eb,
                          const float* __restrict__ prew, int F) {
    int TF = TW * F;
    int c = blockIdx.x * blockDim.x + threadIdx.x;
    if (c >= TF) return;
    int t = c / F, f = c - t * F;
    const float* pr = prew + ((size_t)(t * 3 * F + 2 * F)) * F + f;
    float a0 = 0.f, a1 = 0.f, ab = 0.f;
    for (int j = 0; j < F; j++) {
        float w = pr[(size_t)j * F];
        a0 += ew[j] * w;
        a1 += ew[F + j] * w;
        ab += eb[j] * w;
    }
    d_Cw[c] = a0; d_Cw[TF + c] = a1; d_cb[c] = ab;
}

__global__ void k_pack_wp(const float* __restrict__ postw, int F) {
    int F4 = 4 * F;
    int tot = TW * F4 * 192;
    int idx = blockIdx.x * blockDim.x + threadIdx.x;
    if (idx >= tot) return;
    int t = idx / (F4 * 192);
    int rem = idx - t * (F4 * 192);
    int r = rem / 192;
    int q = rem - r * 192;
    float v = 0.0f;
    if (q < 150) {
        int k = q / 50, o = q - k * 50;
        v = postw[((size_t)(t * 13 * F + F + k * F4 + r)) * 50 + o];
    }
    d_Wp[idx] = v;
}

__global__ void k_pack_wh(const float* __restrict__ postw, int F) {
    int tot = TW * F * 64;
    int idx = blockIdx.x * blockDim.x + threadIdx.x;
    if (idx >= tot) return;
    int t = idx / (F * 64);
    int rem = idx - t * (F * 64);
    int r = rem / 64;
    int o = rem - r * 64;
    d_Wh[idx] = (o < 50) ? postw[((size_t)(t * 13 * F + r)) * 50 + o] : 0.0f;
}

// ---------------- aggregation (mean / min / max / std) ----------------
__global__ void k_agg(const int* __restrict__ src, const float* __restrict__ eattr, int F) {
    int TF = TW * F, ABW = 2 * TF;
    int n = blockIdx.y;
    int c = blockIdx.x * blockDim.x + threadIdx.x;
    if (c >= TF) return;
    float a  = d_AB[(size_t)n * ABW + c];
    float w0 = d_Cw[c], w1 = d_Cw[TF + c], wb = d_cb[c];
    int s = d_off[n], e = d_off[n + 1];
    float sum = 0.f, ss = 0.f, mn = 3.402823466e38f, mx = -3.402823466e38f;
    for (int p = s; p < e; p++) {
        int eid = d_csr[p];
        int sj = src[eid];
        float v = a + d_AB[(size_t)sj * ABW + TF + c]
                + eattr[2 * eid] * w0 + eattr[2 * eid + 1] * w1 + wb;
        sum += v; ss += v * v;
        mn = fminf(mn, v); mx = fmaxf(mx, v);
    }
    if (e == s) { mn = 0.f; mx = 0.f; }
    float dc = d_degc[n];
    float mean = sum / dc;
    float var = fmaxf(ss / dc - mean * mean, 0.f);
    int t = c / F, f = c - t * F;
    float* o = d_agg + (size_t)n * (4 * TF) + (size_t)t * 4 * F;
    o[f]         = mean;
    o[F + f]     = mn;
    o[2 * F + f] = mx;
    o[3 * F + f] = sqrtf(var + 1e-5f);
}

// out[n, t*50+o] = Yh + Ya_plain + amp*Ya_amp + att*Ya_att
__global__ void k_combine() {
    int idx = blockIdx.x * blockDim.x + threadIdx.x;
    if (idx >= NN * 300) return;
    int n = idx / 300, c = idx - n * 300;
    int t = c / 50, o = c - t * 50;
    const float* ya = d_Ya + (size_t)n * 900 + t * 150;
    d_o[idx] = d_Yh[idx] + ya[o] + d_amp[n] * ya[50 + o] + d_att[n] * ya[100 + o];
}

// ---------------- tf32 tensor-core GEMM: C = A@B (+bias)(+relu) ----------------
// BM=128 x BN tile, BK=16, 256 threads (8 warps: 4 along M x 2 along N).
// Each warp: 32 x (BN/2). mma.sync m16n8k8 tf32, fp32 accumulate.
// Requires: lda%4==0, ldb%4==0, K%4==0, 16B-aligned bases. Ndb = physical B width.
template<int BN>
__global__ void __launch_bounds__(256, 2)
k_mma(int M, int Nd, int Ndb, int K,
      const float* __restrict__ A, int lda, long long sA,
      const float* __restrict__ B, int ldb, long long sB,
      float* __restrict__ C, int ldc, long long sC,
      const float* __restrict__ bias, long long sBias, int relu) {
    constexpr int BM = 128, BK = 16;
    constexpr int WN = BN / 2;          // warp col span
    constexpr int NT = WN / 8;          // n8 tiles per warp
    constexpr int AST = 20;             // As row stride (bank-conflict free)
    constexpr int BST = BN + 8;         // Bs row stride (bank-conflict free)
    constexpr int NB4 = BK * BN / 4;    // B float4 slots per stage
    constexpr int BI  = NB4 / 256;      // B float4 per thread (1 or 2)

    __shared__ float As[2][BM][AST];
    __shared__ float Bs[2][BK][BST];

    A += (size_t)blockIdx.z * sA;
    B += (size_t)blockIdx.z * sB;
    C += (size_t)blockIdx.z * sC;
    if (bias) bias += (size_t)blockIdx.z * sBias;

    const int tid = threadIdx.x;
    const int wid = tid >> 5, lane = tid & 31;
    const int g = lane >> 2, q = lane & 3;
    const int wm = (wid & 3) * 32;
    const int wn = (wid >> 2) * WN;
    const int row0 = blockIdx.y * BM, col0 = blockIdx.x * BN;

    float acc[2][NT][4];
#pragma unroll
    for (int mt = 0; mt < 2; mt++)
#pragma unroll
        for (int nt = 0; nt < NT; nt++)
#pragma unroll
            for (int i = 0; i < 4; i++) acc[mt][nt][i] = 0.f;

    const int S = (K + BK - 1) / BK;

    float4 aR[2], bR[BI];

    auto fetch = [&](int s) {
        int k0 = s * BK;
#pragma unroll
        for (int i = 0; i < 2; i++) {
            int sl = tid + 256 * i;
            int m = sl >> 2, kq = (sl & 3) * 4;
            int r = row0 + m, k = k0 + kq;
            float4 v = make_float4(0.f, 0.f, 0.f, 0.f);
            if (r < M && k < K) v = *(const float4*)(A + (size_t)r * lda + k);
            aR[i] = v;
        }
#pragma unroll
        for (int i = 0; i < BI; i++) {
            int sl = tid + 256 * i;
            int k = sl / (BN / 4), nq = (sl % (BN / 4)) * 4;
            int kk = k0 + k, c = col0 + nq;
            float4 v = make_float4(0.f, 0.f, 0.f, 0.f);
            if (kk < K && c < Ndb) v = *(const float4*)(B + (size_t)kk * ldb + c);
            bR[i] = v;
        }
    };

    auto stage = [&](int buf) {
#pragma unroll
        for (int i = 0; i < 2; i++) {
            int sl = tid + 256 * i;
            int m = sl >> 2, kq = (sl & 3) * 4;
            float* p = &As[buf][m][kq];
            p[0] = totf32(aR[i].x); p[1] = totf32(aR[i].y);
            p[2] = totf32(aR[i].z); p[3] = totf32(aR[i].w);
        }
#pragma unroll
        for (int i = 0; i < BI; i++) {
            int sl = tid + 256 * i;
            int k = sl / (BN / 4), nq = (sl % (BN / 4)) * 4;
            float4 v;
            v.x = totf32(bR[i].x); v.y = totf32(bR[i].y);
            v.z = totf32(bR[i].z); v.w = totf32(bR[i].w);
            *(float4*)&Bs[buf][k][nq] = v;
        }
    };

    auto compute = [&](int buf) {
#pragma unroll
        for (int h = 0; h < 2; h++) {
            unsigned a[2][4], b[NT][2];
#pragma unroll
            for (int mt = 0; mt < 2; mt++) {
                int r = wm + mt * 16 + g;
                a[mt][0] = __float_as_uint(As[buf][r    ][h * 8 + q    ]);
                a[mt][1] = __float_as_uint(As[buf][r + 8][h * 8 + q    ]);
                a[mt][2] = __float_as_uint(As[buf][r    ][h * 8 + q + 4]);
                a[mt][3] = __float_as_uint(As[buf][r + 8][h * 8 + q + 4]);
            }
#pragma unroll
            for (int nt = 0; nt < NT; nt++) {
                int c = wn + nt * 8 + g;
                b[nt][0] = __float_as_uint(Bs[buf][h * 8 + q    ][c]);
                b[nt][1] = __float_as_uint(Bs[buf][h * 8 + q + 4][c]);
            }
#pragma unroll
            for (int mt = 0; mt < 2; mt++)
#pragma unroll
                for (int nt = 0; nt < NT; nt++)
                    mma_tf32(acc[mt][nt], a[mt], b[nt]);
        }
    };

    fetch(0); stage(0); __syncthreads();
    for (int s = 0; s < S; s++) {
        if (s + 1 < S) fetch(s + 1);
        compute(s & 1);
        if (s + 1 < S) stage((s + 1) & 1);
        __syncthreads();
    }

    // epilogue
#pragma unroll
    for (int mt = 0; mt < 2; mt++) {
#pragma unroll
        for (int nt = 0; nt < NT; nt++) {
            int c0 = col0 + wn + nt * 8 + 2 * q;
            int r0 = row0 + wm + mt * 16 + g;
#pragma unroll
            for (int half = 0; half < 2; half++) {
                int r = r0 + half * 8;
                if (r >= M) continue;
                float v0 = acc[mt][nt][half * 2 + 0];
                float v1 = acc[mt][nt][half * 2 + 1];
                if (bias) {
                    if (c0     < Nd) v0 += bias[c0];
                    if (c0 + 1 < Nd) v1 += bias[c0 + 1];
                }
                if (relu) { v0 = fmaxf(v0, 0.f); v1 = fmaxf(v1, 0.f); }
                if (c0     < Nd) C[(size_t)r * ldc + c0]     = v0;
                if (c0 + 1 < Nd) C[(size_t)r * ldc + c0 + 1] = v1;
            }
        }
    }
}

// ---------------- pooling + final head ----------------
__global__ void k_pool(const int* __restrict__ batch) {
    int g = blockIdx.x;      // 16
    int c = threadIdx.x;     // 300
    float acc = 0.f;
    for (int n = 0; n < NN; n++)
        if (batch[n] == g) acc += d_h[(size_t)n * 300 + c];
    d_g[g * 300 + c] = acc;
}

__global__ void k_head3(const float* __restrict__ hw3, const float* __restrict__ hb3,
                        float* __restrict__ out) {
    int g = threadIdx.x >> 5;   // 16 warps
    int l = threadIdx.x & 31;
    float s = 0.f;
    for (int c = l; c < 300; c += 32) s += d_g2[g * 300 + c] * hw3[c];
#pragma unroll
    for (int o = 16; o > 0; o >>= 1) s += __shfl_xor_sync(0xffffffffu, s, o);
    if (l == 0) out[g] = fmaxf(s + hb3[0], 0.f);
}

// ---------------- host ----------------
extern "C" void kernel_launch(void* const* d_in, const int* in_sizes, int n_in,
                              void* d_out, int out_size) {
    const float* x      = (const float*)d_in[0];
    const float* eattr  = (const float*)d_in[1];
    const int*   eidx   = (const int*)  d_in[2];
    const int*   batch  = (const int*)  d_in[3];
    const float* dhist  = (const float*)d_in[4];
    const float* ew0    = (const float*)d_in[5];
    const float* eb0    = (const float*)d_in[6];
    const float* prew0  = (const float*)d_in[7];
    const float* preb0  = (const float*)d_in[8];
    const float* postw0 = (const float*)d_in[9];
    const float* postb0 = (const float*)d_in[10];
    const float* linw0  = (const float*)d_in[11];
    const float* linb0  = (const float*)d_in[12];
    const float* ew     = (const float*)d_in[13];
    const float* eb     = (const float*)d_in[14];
    const float* prew   = (const float*)d_in[15];
    const float* preb   = (const float*)d_in[16];
    const float* postw  = (const float*)d_in[17];
    const float* postb  = (const float*)d_in[18];
    const float* linw   = (const float*)d_in[19];
    const float* linb   = (const float*)d_in[20];
    const float* hw1    = (const float*)d_in[21];
    const float* hb1    = (const float*)d_in[22];
    const float* hw2    = (const float*)d_in[23];
    const float* hb2    = (const float*)d_in[24];
    const float* hw3    = (const float*)d_in[25];
    const float* hb3    = (const float*)d_in[26];

    const int* srcA = eidx;
    const int* dstA = eidx + NE;

    float *pAB, *pWAB, *pbAB, *pWp, *pWh, *pAgg, *pYh, *pYa, *pO, *pH, *pG, *pG1, *pG2;
    cudaGetSymbolAddress((void**)&pAB,  d_AB);
    cudaGetSymbolAddress((void**)&pWAB, d_WAB);
    cudaGetSymbolAddress((void**)&pbAB, d_bAB);
    cudaGetSymbolAddress((void**)&pWp,  d_Wp);
    cudaGetSymbolAddress((void**)&pWh,  d_Wh);
    cudaGetSymbolAddress((void**)&pAgg, d_agg);
    cudaGetSymbolAddress((void**)&pYh,  d_Yh);
    cudaGetSymbolAddress((void**)&pYa,  d_Ya);
    cudaGetSymbolAddress((void**)&pO,   d_o);
    cudaGetSymbolAddress((void**)&pH,   d_h);
    cudaGetSymbolAddress((void**)&pG,   d_g);
    cudaGetSymbolAddress((void**)&pG1,  d_g1);
    cudaGetSymbolAddress((void**)&pG2,  d_g2);

    // ---- graph preprocessing (deterministic CSR) ----
    k_init<<<(NN + 255) / 256, 256>>>();
    k_count<<<(NE + 255) / 256, 256>>>(dstA);
    k_avglog<<<1, 64>>>(dhist);
    k_scan<<<1, 1024>>>();
    k_scalars<<<(NN + 255) / 256, 256>>>();
    k_scatter<<<(NE + 255) / 256, 256>>>(dstA);
    k_sortseg<<<(NN + 255) / 256, 256>>>();

    auto layer = [&](int F, const float* hin,
                     const float* ewL, const float* ebL,
                     const float* prewL, const float* prebL,
                     const float* postwL, const float* postbL,
                     const float* linwL, const float* linbL, int relu) {
        int TF = TW * F;
        int P  = ((2 * TF + 127) / 128) * 128;    // padded AB width (3712 / 384)
        k_pack_wab<<<(F * P + 255) / 256, 256>>>(prewL, F, P);
        k_pack_bab<<<(2 * TF + 255) / 256, 256>>>(prebL, F);
        k_pack_cw<<<(TF + 255) / 256, 256>>>(ewL, ebL, prewL, F);
        k_pack_wp<<<(TW * 4 * F * 192 + 255) / 256, 256>>>(postwL, F);
        k_pack_wh<<<(TW * F * 64 + 255) / 256, 256>>>(postwL, F);

        // AB = h @ WAB + biasAB      [N, 2TF]
        {
            dim3 g(P / 128, NN / 128, 1);
            k_mma<128><<<g, 256>>>(NN, 2 * TF, P, F,
                hin, F, 0, pWAB, P, 0, pAB, 2 * TF, 0, pbAB, 0, 0);
        }
        // aggregation -> agg [N, T, 4F]
        {
            dim3 g((TF + 255) / 256, NN, 1);
            k_agg<<<g, 256>>>(srcA, eattr, F);
        }
        // Ya[n,t,150] = agg_t @ Wp_t   (batched over towers, Wp padded to 192)
        {
            dim3 g(3, NN / 128, TW);
            k_mma<64><<<g, 256>>>(NN, 150, 192, 4 * F,
                pAgg, 4 * TF, 4 * F, pWp, 192, (long long)4 * F * 192,
                pYa, 900, 150, nullptr, 0, 0);
        }
        // Yh[n,t,50] = h @ Wh_t + postb[t]   (Wh padded to 64)
        {
            dim3 g(1, NN / 128, TW);
            k_mma<64><<<g, 256>>>(NN, 50, 64, F,
                hin, F, 0, pWh, 64, (long long)F * 64,
                pYh, 300, 50, postbL, 50, 0);
        }
        k_combine<<<(NN * 300 + 255) / 256, 256>>>();
        // h_next = (out @ linw + linb)  [+relu]
        {
            dim3 g(5, NN / 128, 1);
            k_mma<64><<<g, 256>>>(NN, 300, 300, 300,
                pO, 300, 0, linwL, 300, 0, pH, 300, 0, linbL, 0, relu);
        }
    };

    // layer 0 (F=32), relu
    layer(32, x, ew0, eb0, prew0, preb0, postw0, postb0, linw0, linb0, 1);
    // layers 1..4 (F=300), relu on all but last
    for (int l = 0; l < 4; l++) {
        layer(300, pH,
              ew + (size_t)l * 600, eb + (size_t)l * 300,
              prew + (size_t)l * 1620000, preb + (size_t)l * 1800,
              postw + (size_t)l * 1170000, postb + (size_t)l * 300,
              linw + (size_t)l * 90000, linb + (size_t)l * 300,
              (l < 3) ? 1 : 0);
    }

    // global_add_pool + head MLP
    k_pool<<<NG, 300>>>(batch);
    {
        dim3 g(10, 1, 1);
        k_mma<64><<<g, 256>>>(NG, 600, 600, 300,
            pG, 300, 0, hw1, 600, 0, pG1, 600, 0, hb1, 0, 1);
    }
    {
        dim3 g(5, 1, 1);
        k_mma<64><<<g, 256>>>(NG, 300, 300, 600,
            pG1, 600, 0, hw2, 300, 0, pG2, 300, 0, hb2, 0, 1);
    }
    k_head3<<<1, 512>>>(hw3, hb3, (float*)d_out);
}